// round 2
// baseline (speedup 1.0000x reference)
#include <cuda_runtime.h>
#include <cstdint>

// Residual VQ fused kernel for B200 (sm_100a).
// Shapes (fixed by problem): z [65536, 256] f32, codebooks [8, 1024, 256] f32.
// Output assumed: concat(quantized [65536*256], indices [65536*8] as f32, loss [1]).

#define NCB   8
#define KCB   1024
#define DIM   256
#define NROW  65536
#define TM    128      // rows per CTA
#define TN    128      // codewords per n-tile
#define TKC   16       // reduction chunk
#define NTHR  256
#define RST   132      // residual smem row stride (floats), 132*4 % 16 == 0

#define Q_ELEMS   ((size_t)NROW * DIM)            // 16777216
#define IDX_ELEMS ((size_t)NROW * NCB)            // 524288
#define OUT_FULL  (Q_ELEMS + IDX_ELEMS + 1)       // 17301505

typedef unsigned long long ull;

__device__ float g_Wt[(size_t)NCB * DIM * KCB];   // codebooks transposed: [c][d][k], 8 MB
__device__ float g_wnorm[NCB * KCB];              // ||w||^2 per codeword
__device__ float g_loss[NCB];                     // per-step sum of residual^2

__device__ __forceinline__ ull ffma2(ull a, ull b, ull c) {
    ull d;
    asm("fma.rn.f32x2 %0, %1, %2, %3;" : "=l"(d) : "l"(a), "l"(b), "l"(c));
    return d;
}
__device__ __forceinline__ ull dup2(float x) {
    ull r;
    asm("mov.b64 %0, {%1, %1};" : "=l"(r) : "f"(x));
    return r;
}

// ---------------------------------------------------------------------------
// Prologue: transpose codebooks into g_Wt[c][d][k], compute ||w||^2, zero loss.
// grid = 8192 blocks (one per (c,k) codeword), 256 threads (one per d).
// ---------------------------------------------------------------------------
__global__ void rvq_prep_kernel(const float* __restrict__ cb) {
    int b = blockIdx.x;              // b = c*1024 + k
    int c = b >> 10, k = b & 1023;
    int t = threadIdx.x;             // t = d
    float v = cb[(size_t)b * DIM + t];
    g_Wt[(size_t)c * DIM * KCB + (size_t)t * KCB + k] = v;
    float s = v * v;
    #pragma unroll
    for (int o = 16; o > 0; o >>= 1) s += __shfl_down_sync(0xffffffffu, s, o);
    __shared__ float red[8];
    if ((t & 31) == 0) red[t >> 5] = s;
    __syncthreads();
    if (t == 0) {
        float n = 0.f;
        #pragma unroll
        for (int w = 0; w < 8; ++w) n += red[w];
        g_wnorm[b] = n;
    }
    if (b == 0 && t < NCB) g_loss[t] = 0.f;
}

// ---------------------------------------------------------------------------
// Main fused kernel. One CTA = 128 rows, residual resident in SMEM across all
// 8 codebooks. f32x2-packed SGEMM micro-kernel (8x8 per thread), per-row
// argmin, residual update, index + quantized output, loss partial sums.
// Dynamic SMEM layout (floats):
//   [0,      33792) residual transposed  [256][132]
//   [33792,  37888) W double buffer      2 x [16][128]
//   [37888,  41984) candidates (u64)     [128][16]
//   [41984,  42112) per-row ||r||^2      [128]
//   [42112,  42240) best index per row   [128] (int)
//   [42240,  42256) loss warp partials   [8] (pad 16)
//   [42256,  42512) norm scratch         [256]
// ---------------------------------------------------------------------------
__global__ __launch_bounds__(NTHR, 1)
void rvq_main_kernel(const float* __restrict__ z, const float* __restrict__ cb,
                     float* __restrict__ out, int write_extra) {
    extern __shared__ float sm[];
    float* sR   = sm;                      // residual [d][row]
    float* sW   = sm + 33792;              // W tiles
    ull*   sC   = (ull*)(sm + 37888);      // candidates [128][16]
    float* sRn  = sm + 41984;              // row norms
    int*   sBi  = (int*)(sm + 42112);      // best idx
    float* sLr  = sm + 42240;              // loss partials
    float* sScr = sm + 42256;              // scratch [256]

    const int tid  = threadIdx.x;
    const int row0 = blockIdx.x * TM;
    const int rg   = tid & 15;             // row group (8 rows each), 0..15
    const int cg   = tid >> 4;             // col group (8 cols each), 0..15

    // Load z tile transposed into SMEM residual.
    for (int i = tid; i < TM * DIM; i += NTHR) {
        int row = i >> 8, d = i & 255;
        sR[d * RST + row] = z[(size_t)(row0 + row) * DIM + d];
    }
    __syncthreads();

    for (int c = 0; c < NCB; ++c) {
        // ---- per-row ||r||^2 (matches reference's additive constant) ----
        {
            int row = tid & 127, q = tid >> 7;     // q in {0,1}, 128 dims each
            float s = 0.f;
            #pragma unroll 8
            for (int d = q * 128; d < q * 128 + 128; ++d) {
                float r = sR[d * RST + row];
                s = fmaf(r, r, s);
            }
            sScr[q * 128 + row] = s;
        }
        __syncthreads();
        if (tid < TM)
            sRn[tid] = sScr[tid] + sScr[128 + tid];
        __syncthreads();

        float bv[8]; int bi[8];
        #pragma unroll
        for (int i = 0; i < 8; ++i) { bv[i] = __int_as_float(0x7f800000); bi[i] = 0; }

        const float* Wc  = g_Wt + (size_t)c * DIM * KCB;
        const float* wnc = g_wnorm + c * KCB;

        for (int nt = 0; nt < 8; ++nt) {
            const int n0 = nt * TN;
            ull acc[8][4];
            #pragma unroll
            for (int i = 0; i < 8; ++i)
                #pragma unroll
                for (int j = 0; j < 4; ++j) acc[i][j] = 0ull;

            // prefetch chunk 0: 16 x 128 floats = 512 float4, 256 threads x 2
            {
                #pragma unroll
                for (int it = 0; it < 2; ++it) {
                    int idx = tid + it * NTHR;
                    int dd = idx >> 5, j4 = idx & 31;
                    unsigned sa = (unsigned)__cvta_generic_to_shared(sW + dd * TN + j4 * 4);
                    const float* gp = Wc + (size_t)dd * KCB + n0 + j4 * 4;
                    asm volatile("cp.async.ca.shared.global [%0], [%1], 16;" :: "r"(sa), "l"(gp));
                }
                asm volatile("cp.async.commit_group;");
            }

            #pragma unroll 1
            for (int dt = 0; dt < 16; ++dt) {
                if (dt < 15) {
                    const float* base = Wc + (size_t)(dt + 1) * TKC * KCB;
                    float* dstb = sW + ((dt + 1) & 1) * (TKC * TN);
                    #pragma unroll
                    for (int it = 0; it < 2; ++it) {
                        int idx = tid + it * NTHR;
                        int dd = idx >> 5, j4 = idx & 31;
                        unsigned sa = (unsigned)__cvta_generic_to_shared(dstb + dd * TN + j4 * 4);
                        const float* gp = base + (size_t)dd * KCB + n0 + j4 * 4;
                        asm volatile("cp.async.ca.shared.global [%0], [%1], 16;" :: "r"(sa), "l"(gp));
                    }
                    asm volatile("cp.async.commit_group;");
                    asm volatile("cp.async.wait_group 1;");
                } else {
                    asm volatile("cp.async.wait_group 0;");
                }
                __syncthreads();

                const float* As = sR + (dt * TKC) * RST + rg * 8;
                const float* Bs = sW + (dt & 1) * (TKC * TN) + cg * 8;
                #pragma unroll
                for (int dd = 0; dd < TKC; ++dd) {
                    float4 a0 = *(const float4*)(As + dd * RST);
                    float4 a1 = *(const float4*)(As + dd * RST + 4);
                    ulonglong2 bA = *(const ulonglong2*)(Bs + dd * TN);
                    ulonglong2 bB = *(const ulonglong2*)(Bs + dd * TN + 4);
                    float av[8] = {a0.x, a0.y, a0.z, a0.w, a1.x, a1.y, a1.z, a1.w};
                    #pragma unroll
                    for (int i = 0; i < 8; ++i) {
                        ull a2 = dup2(av[i]);
                        acc[i][0] = ffma2(a2, bA.x, acc[i][0]);
                        acc[i][1] = ffma2(a2, bA.y, acc[i][1]);
                        acc[i][2] = ffma2(a2, bB.x, acc[i][2]);
                        acc[i][3] = ffma2(a2, bB.y, acc[i][3]);
                    }
                }
                __syncthreads();
            }

            // epilogue: score = (||r||^2 - 2 s) + ||w||^2, track per-row min
            #pragma unroll
            for (int i = 0; i < 8; ++i) {
                float rn = sRn[rg * 8 + i];
                #pragma unroll
                for (int j = 0; j < 4; ++j) {
                    int k0 = n0 + cg * 8 + j * 2;
                    float2 wn = *(const float2*)(wnc + k0);
                    float slo = __uint_as_float((unsigned)(acc[i][j] & 0xffffffffull));
                    float shi = __uint_as_float((unsigned)(acc[i][j] >> 32));
                    float d0 = __fadd_rn(__fadd_rn(rn, -2.f * slo), wn.x);
                    float d1 = __fadd_rn(__fadd_rn(rn, -2.f * shi), wn.y);
                    if (d0 < bv[i]) { bv[i] = d0; bi[i] = k0; }
                    if (d1 < bv[i]) { bv[i] = d1; bi[i] = k0 + 1; }
                }
            }
        }

        // ---- cross-thread argmin reduction (packed u64: score bits | idx) ----
        // Monotone float->uint map; ties resolve to smallest idx (first min),
        // matching jnp.argmin.
        #pragma unroll
        for (int i = 0; i < 8; ++i) {
            unsigned m = __float_as_uint(bv[i]);
            m = (m & 0x80000000u) ? ~m : (m | 0x80000000u);
            sC[(rg * 8 + i) * 16 + cg] = ((ull)m << 32) | (unsigned)bi[i];
        }
        __syncthreads();
        if (tid < TM) {
            ull best = sC[tid * 16];
            #pragma unroll
            for (int j = 1; j < 16; ++j) {
                ull v = sC[tid * 16 + j];
                if (v < best) best = v;
            }
            int k = (int)(best & 0xffffffffull);
            sBi[tid] = k;
            if (write_extra)
                out[Q_ELEMS + (size_t)(row0 + tid) * NCB + c] = (float)k;
        }
        __syncthreads();

        // ---- residual update + loss partial ----
        {
            int row = tid & 127, q = tid >> 7;
            int k = sBi[row];
            const float4* wp = (const float4*)(cb + ((size_t)c * KCB + k) * DIM + q * 128);
            float ls = 0.f;
            #pragma unroll
            for (int t4 = 0; t4 < 32; ++t4) {
                float4 w = wp[t4];
                int d = q * 128 + t4 * 4;
                float r0 = sR[(d + 0) * RST + row] - w.x; sR[(d + 0) * RST + row] = r0; ls = fmaf(r0, r0, ls);
                float r1 = sR[(d + 1) * RST + row] - w.y; sR[(d + 1) * RST + row] = r1; ls = fmaf(r1, r1, ls);
                float r2 = sR[(d + 2) * RST + row] - w.z; sR[(d + 2) * RST + row] = r2; ls = fmaf(r2, r2, ls);
                float r3 = sR[(d + 3) * RST + row] - w.w; sR[(d + 3) * RST + row] = r3; ls = fmaf(r3, r3, ls);
            }
            #pragma unroll
            for (int o = 16; o > 0; o >>= 1) ls += __shfl_down_sync(0xffffffffu, ls, o);
            if ((tid & 31) == 0) sLr[tid >> 5] = ls;
            __syncthreads();
            if (tid == 0) {
                float tot = 0.f;
                #pragma unroll
                for (int w = 0; w < 8; ++w) tot += sLr[w];
                atomicAdd(&g_loss[c], tot);
            }
            __syncthreads();
        }
    }

    // ---- quantized = z - residual_final ----
    {
        int row = tid & 127, q = tid >> 7;
        const float* zp = z + (size_t)(row0 + row) * DIM + q * 128;
        float* op = out + (size_t)(row0 + row) * DIM + q * 128;
        #pragma unroll
        for (int t4 = 0; t4 < 32; ++t4) {
            float4 zv = *(const float4*)(zp + t4 * 4);
            int d = q * 128 + t4 * 4;
            float4 r;
            r.x = zv.x - sR[(d + 0) * RST + row];
            r.y = zv.y - sR[(d + 1) * RST + row];
            r.z = zv.z - sR[(d + 2) * RST + row];
            r.w = zv.w - sR[(d + 3) * RST + row];
            *(float4*)(op + t4 * 4) = r;
        }
    }
}

// Finish: loss = sum_c mean_c
__global__ void rvq_fin_kernel(float* __restrict__ out) {
    if (threadIdx.x == 0) {
        float l = 0.f;
        #pragma unroll
        for (int c = 0; c < NCB; ++c) l += g_loss[c] * (1.0f / 16777216.0f);
        out[Q_ELEMS + IDX_ELEMS] = l;
    }
}

extern "C" void kernel_launch(void* const* d_in, const int* in_sizes, int n_in,
                              void* d_out, int out_size) {
    const float* z  = (const float*)d_in[0];
    const float* cb = (const float*)d_in[1];
    // Robustness: detect swapped input order by element counts.
    if (n_in >= 2 && in_sizes[0] == NCB * KCB * DIM && in_sizes[1] == NROW * DIM) {
        z  = (const float*)d_in[1];
        cb = (const float*)d_in[0];
    }
    float* out = (float*)d_out;
    int write_extra = ((size_t)out_size >= OUT_FULL) ? 1 : 0;

    static const size_t SMEM_BYTES = 42512 * sizeof(float);  // 170,048 B
    cudaFuncSetAttribute(rvq_main_kernel, cudaFuncAttributeMaxDynamicSharedMemorySize,
                         (int)SMEM_BYTES);

    rvq_prep_kernel<<<NCB * KCB, 256>>>(cb);
    rvq_main_kernel<<<NROW / TM, NTHR, SMEM_BYTES>>>(z, cb, out, write_extra);
    if (write_extra) rvq_fin_kernel<<<1, 32>>>(out);
}

// round 5
// speedup vs baseline: 1.1403x; 1.1403x over previous
#include <cuda_runtime.h>
#include <cstdint>

// Residual VQ fused kernel for B200 (sm_100a).
// z [65536, 256] f32, codebooks [8, 1024, 256] f32.
// Output: concat(quantized [65536*256], indices [65536*8] as f32, loss [1]).

#define NCB   8
#define KCB   1024
#define DIM   256
#define NROW  65536
#define TM    64       // rows per CTA
#define TN    128      // codewords per n-tile
#define TKC   32       // reduction chunk
#define NTHR  256
#define RST   68       // residual smem row stride (floats), 68*4 % 16 == 0
#define NDT   (DIM / TKC)   // 8
#define NNT   (KCB / TN)    // 8

#define Q_ELEMS   ((size_t)NROW * DIM)            // 16777216
#define IDX_ELEMS ((size_t)NROW * NCB)            // 524288
#define OUT_FULL  (Q_ELEMS + IDX_ELEMS + 1)       // 17301505

// SMEM float offsets
#define OFF_W    17408                      // sR = [256][68] = 17408 floats
#define OFF_C    (OFF_W + 2 * TKC * TN)     // sW double buffer = 8192 fl
#define OFF_RN   (OFF_C + 2048)             // sC = 64*16 ull = 2048 fl
#define OFF_BI   (OFF_RN + 64)
#define OFF_SCR  (OFF_BI + 64)
#define SMEM_FL  (OFF_SCR + 256 + 16)       // = 28048 floats = 112,192 B

typedef unsigned long long ull;

__device__ float g_Wt[(size_t)NCB * DIM * KCB];   // codebooks transposed: [c][d][k]
__device__ float g_wnorm[NCB * KCB];              // ||w||^2 per codeword
__device__ float g_loss[NCB];                     // per-step sum of residual^2

__device__ __forceinline__ ull ffma2(ull a, ull b, ull c) {
    ull d;
    asm("fma.rn.f32x2 %0, %1, %2, %3;" : "=l"(d) : "l"(a), "l"(b), "l"(c));
    return d;
}
__device__ __forceinline__ ull dup2(float x) {
    ull r;
    asm("mov.b64 %0, {%1, %1};" : "=l"(r) : "f"(x));
    return r;
}

// ---------------------------------------------------------------------------
// Prologue: transpose codebooks into g_Wt[c][d][k], ||w||^2, zero loss.
// ---------------------------------------------------------------------------
__global__ void rvq_prep_kernel(const float* __restrict__ cb) {
    int b = blockIdx.x;              // b = c*1024 + k
    int c = b >> 10, k = b & 1023;
    int t = threadIdx.x;             // t = d
    float v = cb[(size_t)b * DIM + t];
    g_Wt[(size_t)c * DIM * KCB + (size_t)t * KCB + k] = v;
    float s = v * v;
    #pragma unroll
    for (int o = 16; o > 0; o >>= 1) s += __shfl_down_sync(0xffffffffu, s, o);
    __shared__ float red[8];
    if ((t & 31) == 0) red[t >> 5] = s;
    __syncthreads();
    if (t == 0) {
        float n = 0.f;
        #pragma unroll
        for (int w = 0; w < 8; ++w) n += red[w];
        g_wnorm[b] = n;
    }
    if (b == 0 && t < NCB) g_loss[t] = 0.f;
}

// ---------------------------------------------------------------------------
// Main fused kernel: 64 rows/CTA resident in SMEM across all 8 codebooks.
// f32x2 SGEMM (4x8 per thread), fused norm-in-residual-update, 2 CTAs/SM.
// ---------------------------------------------------------------------------
__global__ __launch_bounds__(NTHR, 2)
void rvq_main_kernel(const float* __restrict__ z, const float* __restrict__ cb,
                     float* __restrict__ out, int write_extra) {
    extern __shared__ float sm[];
    float* sR  = sm;                       // residual [d][row], stride RST
    float* sW  = sm + OFF_W;               // B tiles, 2 x [TKC][TN]
    ull*   sC  = (ull*)(sm + OFF_C);       // candidates [64][16]
    float* sRn = sm + OFF_RN;              // row norms [64]
    int*   sBi = (int*)(sm + OFF_BI);      // best idx [64]
    float* sScr= sm + OFF_SCR;             // scratch [256]

    const int tid  = threadIdx.x;
    const int row0 = blockIdx.x * TM;
    const int cg   = tid & 15;             // col group (8 cols), 0..15
    const int rg   = tid >> 4;             // row group (4 rows), 0..15
    // permuted physical 16B-block offsets for this thread's two B blocks
    const int b0 = 2 * cg, b1 = 2 * cg + 1;
    const int pb0 = (b0 ^ ((b0 >> 3) & 1)) * 4;
    const int pb1 = (b1 ^ ((b1 >> 3) & 1)) * 4;

    // Load z tile transposed into SMEM residual (coalesced on d).
    for (int i = tid; i < TM * DIM; i += NTHR) {
        int row = i >> 8, d = i & 255;
        sR[d * RST + row] = z[(size_t)(row0 + row) * DIM + d];
    }
    __syncthreads();

    // Initial per-row ||r||^2 (c = 0 only; later steps get it from the update).
    {
        int q = tid >> 6, row = tid & 63;
        float s = 0.f;
        #pragma unroll 16
        for (int d = q * 64; d < q * 64 + 64; ++d) {
            float r = sR[d * RST + row];
            s = fmaf(r, r, s);
        }
        sScr[q * 64 + row] = s;
    }
    __syncthreads();
    if (tid < TM)
        sRn[tid] = (sScr[tid] + sScr[64 + tid]) + (sScr[128 + tid] + sScr[192 + tid]);
    __syncthreads();

    for (int c = 0; c < NCB; ++c) {
        float bv[4]; int bi[4];
        #pragma unroll
        for (int i = 0; i < 4; ++i) { bv[i] = __int_as_float(0x7f800000); bi[i] = 0; }

        const float* Wc  = g_Wt + (size_t)c * DIM * KCB;
        const float* wnc = g_wnorm + c * KCB;

        for (int nt = 0; nt < NNT; ++nt) {
            const int n0 = nt * TN;
            ull acc[4][4];
            #pragma unroll
            for (int i = 0; i < 4; ++i)
                #pragma unroll
                for (int j = 0; j < 4; ++j) acc[i][j] = 0ull;

            // prefetch chunk 0: TKC x TN floats = 1024 float4, 256 thr x 4
            {
                #pragma unroll
                for (int it = 0; it < 4; ++it) {
                    int idx = tid + it * NTHR;
                    int dd = idx >> 5, j4 = idx & 31;
                    int pj = j4 ^ ((j4 >> 3) & 1);
                    unsigned sa = (unsigned)__cvta_generic_to_shared(sW + dd * TN + pj * 4);
                    const float* gp = Wc + (size_t)dd * KCB + n0 + j4 * 4;
                    asm volatile("cp.async.ca.shared.global [%0], [%1], 16;" :: "r"(sa), "l"(gp));
                }
                asm volatile("cp.async.commit_group;");
            }

            #pragma unroll 1
            for (int dt = 0; dt < NDT; ++dt) {
                if (dt < NDT - 1) {
                    const float* base = Wc + (size_t)(dt + 1) * TKC * KCB;
                    float* dstb = sW + ((dt + 1) & 1) * (TKC * TN);
                    #pragma unroll
                    for (int it = 0; it < 4; ++it) {
                        int idx = tid + it * NTHR;
                        int dd = idx >> 5, j4 = idx & 31;
                        int pj = j4 ^ ((j4 >> 3) & 1);
                        unsigned sa = (unsigned)__cvta_generic_to_shared(dstb + dd * TN + pj * 4);
                        const float* gp = base + (size_t)dd * KCB + n0 + j4 * 4;
                        asm volatile("cp.async.ca.shared.global [%0], [%1], 16;" :: "r"(sa), "l"(gp));
                    }
                    asm volatile("cp.async.commit_group;");
                    asm volatile("cp.async.wait_group 1;");
                } else {
                    asm volatile("cp.async.wait_group 0;");
                }
                __syncthreads();

                const float* As = sR + (dt * TKC) * RST + rg * 4;
                const float* B0 = sW + (dt & 1) * (TKC * TN) + pb0;
                const float* B1 = sW + (dt & 1) * (TKC * TN) + pb1;
                #pragma unroll 8
                for (int dd = 0; dd < TKC; ++dd) {
                    float4 a0 = *(const float4*)(As + dd * RST);
                    ulonglong2 bA = *(const ulonglong2*)(B0 + dd * TN);
                    ulonglong2 bB = *(const ulonglong2*)(B1 + dd * TN);
                    float av[4] = {a0.x, a0.y, a0.z, a0.w};
                    #pragma unroll
                    for (int i = 0; i < 4; ++i) {
                        ull a2 = dup2(av[i]);
                        acc[i][0] = ffma2(a2, bA.x, acc[i][0]);
                        acc[i][1] = ffma2(a2, bA.y, acc[i][1]);
                        acc[i][2] = ffma2(a2, bB.x, acc[i][2]);
                        acc[i][3] = ffma2(a2, bB.y, acc[i][3]);
                    }
                }
                __syncthreads();
            }

            // epilogue: score = (||r||^2 - 2 s) + ||w||^2, per-row running min
            #pragma unroll
            for (int i = 0; i < 4; ++i) {
                float rn = sRn[rg * 4 + i];
                #pragma unroll
                for (int j = 0; j < 4; ++j) {
                    int k0 = n0 + cg * 8 + j * 2;
                    float2 wn = *(const float2*)(wnc + k0);
                    float slo = __uint_as_float((unsigned)(acc[i][j] & 0xffffffffull));
                    float shi = __uint_as_float((unsigned)(acc[i][j] >> 32));
                    float d0 = __fadd_rn(__fadd_rn(rn, -2.f * slo), wn.x);
                    float d1 = __fadd_rn(__fadd_rn(rn, -2.f * shi), wn.y);
                    if (d0 < bv[i]) { bv[i] = d0; bi[i] = k0; }
                    if (d1 < bv[i]) { bv[i] = d1; bi[i] = k0 + 1; }
                }
            }
        }

        // ---- cross-thread argmin (packed u64: ordered score bits | idx) ----
        // Ties resolve to smallest idx (first min), matching jnp.argmin.
        #pragma unroll
        for (int i = 0; i < 4; ++i) {
            unsigned m = __float_as_uint(bv[i]);
            m = (m & 0x80000000u) ? ~m : (m | 0x80000000u);
            sC[(rg * 4 + i) * 16 + cg] = ((ull)m << 32) | (unsigned)bi[i];
        }
        __syncthreads();
        if (tid < TM) {
            ull best = sC[tid * 16];
            #pragma unroll
            for (int j = 1; j < 16; ++j) {
                ull v = sC[tid * 16 + j];
                if (v < best) best = v;
            }
            int k = (int)(best & 0xffffffffull);
            sBi[tid] = k;
            if (write_extra)
                out[Q_ELEMS + (size_t)(row0 + tid) * NCB + c] = (float)k;
        }
        __syncthreads();

        // ---- residual update; partial sums double as next step's ||r||^2 ----
        {
            int q = tid >> 6, row = tid & 63;
            int k = sBi[row];
            const float4* wp = (const float4*)(cb + ((size_t)c * KCB + k) * DIM + q * 64);
            float ls = 0.f;
            #pragma unroll
            for (int t4 = 0; t4 < 16; ++t4) {
                float4 w = wp[t4];
                int d = q * 64 + t4 * 4;
                float r0 = sR[(d + 0) * RST + row] - w.x; sR[(d + 0) * RST + row] = r0; ls = fmaf(r0, r0, ls);
                float r1 = sR[(d + 1) * RST + row] - w.y; sR[(d + 1) * RST + row] = r1; ls = fmaf(r1, r1, ls);
                float r2 = sR[(d + 2) * RST + row] - w.z; sR[(d + 2) * RST + row] = r2; ls = fmaf(r2, r2, ls);
                float r3 = sR[(d + 3) * RST + row] - w.w; sR[(d + 3) * RST + row] = r3; ls = fmaf(r3, r3, ls);
            }
            sScr[q * 64 + row] = ls;
        }
        __syncthreads();
        if (tid < TM) {
            float rn = (sScr[tid] + sScr[64 + tid]) + (sScr[128 + tid] + sScr[192 + tid]);
            sRn[tid] = rn;                 // ||r_{c+1}||^2 for next step's scores
            // loss_c = sum over rows of rn
            #pragma unroll
            for (int o = 16; o > 0; o >>= 1) rn += __shfl_down_sync(0xffffffffu, rn, o);
            if ((tid & 31) == 0) atomicAdd(&g_loss[c], rn);
        }
        __syncthreads();
    }

    // ---- quantized = z - residual_final ----
    {
        int q = tid >> 6, row = tid & 63;
        const float* zp = z + (size_t)(row0 + row) * DIM + q * 64;
        float* op = out + (size_t)(row0 + row) * DIM + q * 64;
        #pragma unroll
        for (int t4 = 0; t4 < 16; ++t4) {
            float4 zv = *(const float4*)(zp + t4 * 4);
            int d = q * 64 + t4 * 4;
            float4 r;
            r.x = zv.x - sR[(d + 0) * RST + row];
            r.y = zv.y - sR[(d + 1) * RST + row];
            r.z = zv.z - sR[(d + 2) * RST + row];
            r.w = zv.w - sR[(d + 3) * RST + row];
            *(float4*)(op + t4 * 4) = r;
        }
    }
}

// Finish: loss = sum_c mean_c
__global__ void rvq_fin_kernel(float* __restrict__ out) {
    if (threadIdx.x == 0) {
        float l = 0.f;
        #pragma unroll
        for (int c = 0; c < NCB; ++c) l += g_loss[c] * (1.0f / 16777216.0f);
        out[Q_ELEMS + IDX_ELEMS] = l;
    }
}

extern "C" void kernel_launch(void* const* d_in, const int* in_sizes, int n_in,
                              void* d_out, int out_size) {
    const float* z  = (const float*)d_in[0];
    const float* cb = (const float*)d_in[1];
    if (n_in >= 2 && in_sizes[0] == NCB * KCB * DIM && in_sizes[1] == NROW * DIM) {
        z  = (const float*)d_in[1];
        cb = (const float*)d_in[0];
    }
    float* out = (float*)d_out;
    int write_extra = ((size_t)out_size >= OUT_FULL) ? 1 : 0;

    static const size_t SMEM_BYTES = SMEM_FL * sizeof(float);  // 112,192 B
    cudaFuncSetAttribute(rvq_main_kernel, cudaFuncAttributeMaxDynamicSharedMemorySize,
                         (int)SMEM_BYTES);

    rvq_prep_kernel<<<NCB * KCB, 256>>>(cb);
    rvq_main_kernel<<<NROW / TM, NTHR, SMEM_BYTES>>>(z, cb, out, write_extra);
    if (write_extra) rvq_fin_kernel<<<1, 32>>>(out);
}

// round 6
// speedup vs baseline: 1.1571x; 1.0147x over previous
#include <cuda_runtime.h>
#include <cstdint>

// Residual VQ fused kernel for B200 (sm_100a).
// z [65536, 256] f32, codebooks [8, 1024, 256] f32.
// Output: concat(quantized [65536*256], indices [65536*8] as f32, loss [1]).

#define NCB   8
#define KCB   1024
#define DIM   256
#define NROW  65536
#define TM    64       // rows per CTA
#define TN    128      // codewords per n-tile
#define TKC   32       // reduction chunk
#define NTHR  256
#define RST   68       // residual smem row stride (floats), 68*4 % 16 == 0
#define NDT   (DIM / TKC)   // 8
#define NNT   (KCB / TN)    // 8

#define Q_ELEMS   ((size_t)NROW * DIM)            // 16777216
#define IDX_ELEMS ((size_t)NROW * NCB)            // 524288
#define OUT_FULL  (Q_ELEMS + IDX_ELEMS + 1)       // 17301505

// SMEM float offsets
#define OFF_W    17408                      // sR = [256][68] = 17408 floats
#define OFF_RN   (OFF_W + 2 * TKC * TN)     // sW double buffer = 8192 fl
#define OFF_BI   (OFF_RN + 64)
#define OFF_SCR  (OFF_BI + 64)
#define SMEM_FL  (OFF_SCR + 256 + 16)       // = 25952 floats = 103,808 B

typedef unsigned long long ull;

__device__ float g_Wt[(size_t)NCB * DIM * KCB];   // codebooks transposed: [c][d][k]
__device__ float g_wnorm[NCB * KCB];              // ||w||^2 per codeword
__device__ float g_loss[NCB];                     // per-step sum of residual^2
__device__ int   g_count;                         // CTA completion counter

__device__ __forceinline__ ull ffma2(ull a, ull b, ull c) {
    ull d;
    asm("fma.rn.f32x2 %0, %1, %2, %3;" : "=l"(d) : "l"(a), "l"(b), "l"(c));
    return d;
}
__device__ __forceinline__ ull dup2(float x) {
    ull r;
    asm("mov.b64 %0, {%1, %1};" : "=l"(r) : "f"(x));
    return r;
}

// ---------------------------------------------------------------------------
// Prologue: transpose codebooks into g_Wt[c][d][k], ||w||^2, zero loss+count.
// ---------------------------------------------------------------------------
__global__ void rvq_prep_kernel(const float* __restrict__ cb) {
    int b = blockIdx.x;              // b = c*1024 + k
    int c = b >> 10, k = b & 1023;
    int t = threadIdx.x;             // t = d
    float v = cb[(size_t)b * DIM + t];
    g_Wt[(size_t)c * DIM * KCB + (size_t)t * KCB + k] = v;
    float s = v * v;
    #pragma unroll
    for (int o = 16; o > 0; o >>= 1) s += __shfl_down_sync(0xffffffffu, s, o);
    __shared__ float red[8];
    if ((t & 31) == 0) red[t >> 5] = s;
    __syncthreads();
    if (t == 0) {
        float n = 0.f;
        #pragma unroll
        for (int w = 0; w < 8; ++w) n += red[w];
        g_wnorm[b] = n;
    }
    if (b == 0 && t < NCB) g_loss[t] = 0.f;
    if (b == 0 && t == NCB) g_count = 0;
}

// ---------------------------------------------------------------------------
// Main fused kernel: 64 rows/CTA resident in SMEM across all 8 codebooks.
// f32x2 SGEMM (4x8 per thread), shuffle argmin, fused norms, 2 CTAs/SM.
// Last CTA writes the final loss (fin kernel folded in).
// ---------------------------------------------------------------------------
__global__ __launch_bounds__(NTHR, 2)
void rvq_main_kernel(const float* __restrict__ z, const float* __restrict__ cb,
                     float* __restrict__ out, int write_extra) {
    extern __shared__ float sm[];
    float* sR  = sm;                       // residual [d][row], stride RST
    float* sW  = sm + OFF_W;               // B tiles, 2 x [TKC][TN]
    float* sRn = sm + OFF_RN;              // row norms [64]
    int*   sBi = (int*)(sm + OFF_BI);      // best idx [64]
    float* sScr= sm + OFF_SCR;             // scratch [256]

    const int tid  = threadIdx.x;
    const int row0 = blockIdx.x * TM;
    const int cg   = tid & 15;             // col group (8 cols), 0..15
    const int rg   = tid >> 4;             // row group (4 rows), 0..15
    // permuted physical 16B-block offsets for this thread's two B blocks
    const int b0 = 2 * cg, b1 = 2 * cg + 1;
    const int pb0 = (b0 ^ ((b0 >> 3) & 1)) * 4;
    const int pb1 = (b1 ^ ((b1 >> 3) & 1)) * 4;

    // Load z tile transposed into SMEM residual (coalesced on d).
    for (int i = tid; i < TM * DIM; i += NTHR) {
        int row = i >> 8, d = i & 255;
        sR[d * RST + row] = z[(size_t)(row0 + row) * DIM + d];
    }
    __syncthreads();

    // Initial per-row ||r||^2 (c = 0 only; later steps get it from the update).
    {
        int q = tid >> 6, row = tid & 63;
        float s = 0.f;
        #pragma unroll 16
        for (int d = q * 64; d < q * 64 + 64; ++d) {
            float r = sR[d * RST + row];
            s = fmaf(r, r, s);
        }
        sScr[q * 64 + row] = s;
    }
    __syncthreads();
    if (tid < TM)
        sRn[tid] = (sScr[tid] + sScr[64 + tid]) + (sScr[128 + tid] + sScr[192 + tid]);
    __syncthreads();

    for (int c = 0; c < NCB; ++c) {
        float bv[4]; int bi[4];
        #pragma unroll
        for (int i = 0; i < 4; ++i) { bv[i] = __int_as_float(0x7f800000); bi[i] = 0; }

        // per-row norms for this codebook, hoisted to registers
        float rn[4];
        #pragma unroll
        for (int i = 0; i < 4; ++i) rn[i] = sRn[rg * 4 + i];

        const float* Wc  = g_Wt + (size_t)c * DIM * KCB;
        const float* wnc = g_wnorm + c * KCB;

        for (int nt = 0; nt < NNT; ++nt) {
            const int n0 = nt * TN;

            // prefetch ||w||^2 for this thread's 8 columns (hidden under GEMM)
            float2 wn[4];
            #pragma unroll
            for (int j = 0; j < 4; ++j)
                wn[j] = *(const float2*)(wnc + n0 + cg * 8 + j * 2);

            ull acc[4][4];
            #pragma unroll
            for (int i = 0; i < 4; ++i)
                #pragma unroll
                for (int j = 0; j < 4; ++j) acc[i][j] = 0ull;

            // prefetch chunk 0: TKC x TN floats = 1024 float4, 256 thr x 4
            {
                #pragma unroll
                for (int it = 0; it < 4; ++it) {
                    int idx = tid + it * NTHR;
                    int dd = idx >> 5, j4 = idx & 31;
                    int pj = j4 ^ ((j4 >> 3) & 1);
                    unsigned sa = (unsigned)__cvta_generic_to_shared(sW + dd * TN + pj * 4);
                    const float* gp = Wc + (size_t)dd * KCB + n0 + j4 * 4;
                    asm volatile("cp.async.ca.shared.global [%0], [%1], 16;" :: "r"(sa), "l"(gp));
                }
                asm volatile("cp.async.commit_group;");
            }

            #pragma unroll 1
            for (int dt = 0; dt < NDT; ++dt) {
                if (dt < NDT - 1) {
                    const float* base = Wc + (size_t)(dt + 1) * TKC * KCB;
                    float* dstb = sW + ((dt + 1) & 1) * (TKC * TN);
                    #pragma unroll
                    for (int it = 0; it < 4; ++it) {
                        int idx = tid + it * NTHR;
                        int dd = idx >> 5, j4 = idx & 31;
                        int pj = j4 ^ ((j4 >> 3) & 1);
                        unsigned sa = (unsigned)__cvta_generic_to_shared(dstb + dd * TN + pj * 4);
                        const float* gp = base + (size_t)dd * KCB + n0 + j4 * 4;
                        asm volatile("cp.async.ca.shared.global [%0], [%1], 16;" :: "r"(sa), "l"(gp));
                    }
                    asm volatile("cp.async.commit_group;");
                    asm volatile("cp.async.wait_group 1;");
                } else {
                    asm volatile("cp.async.wait_group 0;");
                }
                __syncthreads();

                const float* As = sR + (dt * TKC) * RST + rg * 4;
                const float* B0 = sW + (dt & 1) * (TKC * TN) + pb0;
                const float* B1 = sW + (dt & 1) * (TKC * TN) + pb1;
                #pragma unroll 8
                for (int dd = 0; dd < TKC; ++dd) {
                    float4 a0 = *(const float4*)(As + dd * RST);
                    ulonglong2 bA = *(const ulonglong2*)(B0 + dd * TN);
                    ulonglong2 bB = *(const ulonglong2*)(B1 + dd * TN);
                    float av[4] = {a0.x, a0.y, a0.z, a0.w};
                    #pragma unroll
                    for (int i = 0; i < 4; ++i) {
                        ull a2 = dup2(av[i]);
                        acc[i][0] = ffma2(a2, bA.x, acc[i][0]);
                        acc[i][1] = ffma2(a2, bA.y, acc[i][1]);
                        acc[i][2] = ffma2(a2, bB.x, acc[i][2]);
                        acc[i][3] = ffma2(a2, bB.y, acc[i][3]);
                    }
                }
                __syncthreads();
            }

            // epilogue: score = (||r||^2 - 2 s) + ||w||^2, per-row running min
            #pragma unroll
            for (int i = 0; i < 4; ++i) {
                #pragma unroll
                for (int j = 0; j < 4; ++j) {
                    int k0 = n0 + cg * 8 + j * 2;
                    float slo = __uint_as_float((unsigned)(acc[i][j] & 0xffffffffull));
                    float shi = __uint_as_float((unsigned)(acc[i][j] >> 32));
                    float d0 = __fadd_rn(__fadd_rn(rn[i], -2.f * slo), wn[j].x);
                    float d1 = __fadd_rn(__fadd_rn(rn[i], -2.f * shi), wn[j].y);
                    if (d0 < bv[i]) { bv[i] = d0; bi[i] = k0; }
                    if (d1 < bv[i]) { bv[i] = d1; bi[i] = k0 + 1; }
                }
            }
        }

        // ---- shuffle argmin over the 16 cg lanes (a half-warp per rg) ----
        // Packed u64: ordered score bits | idx; min → first-min tie-break.
        #pragma unroll
        for (int i = 0; i < 4; ++i) {
            unsigned m = __float_as_uint(bv[i]);
            m = (m & 0x80000000u) ? ~m : (m | 0x80000000u);
            ull v = ((ull)m << 32) | (unsigned)bi[i];
            #pragma unroll
            for (int off = 1; off < 16; off <<= 1) {
                ull o = __shfl_xor_sync(0xffffffffu, v, off);
                if (o < v) v = o;
            }
            if (cg == 0) {
                int k = (int)(v & 0xffffffffull);
                int row = rg * 4 + i;
                sBi[row] = k;
                if (write_extra)
                    out[Q_ELEMS + (size_t)(row0 + row) * NCB + c] = (float)k;
            }
        }
        __syncthreads();

        // ---- residual update; partial sums double as next step's ||r||^2 ----
        {
            int q = tid >> 6, row = tid & 63;
            int k = sBi[row];
            const float4* wp = (const float4*)(cb + ((size_t)c * KCB + k) * DIM + q * 64);
            float ls = 0.f;
            #pragma unroll
            for (int t4 = 0; t4 < 16; ++t4) {
                float4 w = wp[t4];
                int d = q * 64 + t4 * 4;
                float r0 = sR[(d + 0) * RST + row] - w.x; sR[(d + 0) * RST + row] = r0; ls = fmaf(r0, r0, ls);
                float r1 = sR[(d + 1) * RST + row] - w.y; sR[(d + 1) * RST + row] = r1; ls = fmaf(r1, r1, ls);
                float r2 = sR[(d + 2) * RST + row] - w.z; sR[(d + 2) * RST + row] = r2; ls = fmaf(r2, r2, ls);
                float r3 = sR[(d + 3) * RST + row] - w.w; sR[(d + 3) * RST + row] = r3; ls = fmaf(r3, r3, ls);
            }
            sScr[q * 64 + row] = ls;
        }
        __syncthreads();
        if (tid < TM) {
            float rn2 = (sScr[tid] + sScr[64 + tid]) + (sScr[128 + tid] + sScr[192 + tid]);
            sRn[tid] = rn2;                // ||r_{c+1}||^2 for next step's scores
            #pragma unroll
            for (int o = 16; o > 0; o >>= 1) rn2 += __shfl_down_sync(0xffffffffu, rn2, o);
            if ((tid & 31) == 0) atomicAdd(&g_loss[c], rn2);
        }
        __syncthreads();
    }

    // ---- quantized = z - residual_final ----
    {
        int q = tid >> 6, row = tid & 63;
        const float* zp = z + (size_t)(row0 + row) * DIM + q * 64;
        float* op = out + (size_t)(row0 + row) * DIM + q * 64;
        #pragma unroll
        for (int t4 = 0; t4 < 16; ++t4) {
            float4 zv = *(const float4*)(zp + t4 * 4);
            int d = q * 64 + t4 * 4;
            float4 r;
            r.x = zv.x - sR[(d + 0) * RST + row];
            r.y = zv.y - sR[(d + 1) * RST + row];
            r.z = zv.z - sR[(d + 2) * RST + row];
            r.w = zv.w - sR[(d + 3) * RST + row];
            *(float4*)(op + t4 * 4) = r;
        }
    }

    // ---- last CTA writes the loss (fin kernel folded in) ----
    if (tid == 0) {
        __threadfence();
        int prev = atomicAdd(&g_count, 1);
        if (prev == (int)gridDim.x - 1) {
            float l = 0.f;
            #pragma unroll
            for (int cc = 0; cc < NCB; ++cc) l += g_loss[cc] * (1.0f / 16777216.0f);
            if (write_extra) out[Q_ELEMS + IDX_ELEMS] = l;
        }
    }
}

extern "C" void kernel_launch(void* const* d_in, const int* in_sizes, int n_in,
                              void* d_out, int out_size) {
    const float* z  = (const float*)d_in[0];
    const float* cb = (const float*)d_in[1];
    if (n_in >= 2 && in_sizes[0] == NCB * KCB * DIM && in_sizes[1] == NROW * DIM) {
        z  = (const float*)d_in[1];
        cb = (const float*)d_in[0];
    }
    float* out = (float*)d_out;
    int write_extra = ((size_t)out_size >= OUT_FULL) ? 1 : 0;

    static const size_t SMEM_BYTES = SMEM_FL * sizeof(float);  // 103,808 B
    cudaFuncSetAttribute(rvq_main_kernel, cudaFuncAttributeMaxDynamicSharedMemorySize,
                         (int)SMEM_BYTES);

    rvq_prep_kernel<<<NCB * KCB, 256>>>(cb);
    rvq_main_kernel<<<NROW / TM, NTHR, SMEM_BYTES>>>(z, cb, out, write_extra);
}

// round 7
// speedup vs baseline: 1.2758x; 1.1026x over previous
#include <cuda_runtime.h>
#include <cstdint>

// Residual VQ fused kernel for B200 (sm_100a).
// z [65536, 256] f32, codebooks [8, 1024, 256] f32.
// Output: concat(quantized [65536*256], indices [65536*8] as f32, loss [1]).

#define NCB   8
#define KCB   1024
#define DIM   256
#define NROW  65536
#define TM    64       // rows per CTA
#define TN    128      // codewords per n-tile
#define TKC   32       // reduction chunk
#define NTHR  128
#define RST   68       // residual smem row stride (floats), 68*4 % 16 == 0
#define NDT   (DIM / TKC)   // 8
#define NNT   (KCB / TN)    // 8

#define Q_ELEMS   ((size_t)NROW * DIM)            // 16777216
#define IDX_ELEMS ((size_t)NROW * NCB)            // 524288
#define OUT_FULL  (Q_ELEMS + IDX_ELEMS + 1)       // 17301505

// SMEM float offsets
#define OFF_W    17408                      // sR = [256][68] = 17408 floats
#define OFF_RN   (OFF_W + 2 * TKC * TN)     // sW double buffer = 8192 fl
#define OFF_BI   (OFF_RN + 64)
#define OFF_SCR  (OFF_BI + 64)
#define SMEM_FL  (OFF_SCR + 128 + 16)       // = 25680 floats = 102,720 B

typedef unsigned long long ull;

__device__ float g_Wt[(size_t)NCB * DIM * KCB];   // codebooks transposed: [c][d][k]
__device__ float g_wnorm[NCB * KCB];              // ||w||^2 per codeword
__device__ float g_loss[NCB];                     // per-step sum of residual^2
__device__ int   g_count;                         // CTA completion counter

__device__ __forceinline__ ull ffma2(ull a, ull b, ull c) {
    ull d;
    asm("fma.rn.f32x2 %0, %1, %2, %3;" : "=l"(d) : "l"(a), "l"(b), "l"(c));
    return d;
}
__device__ __forceinline__ ull dup2(float x) {
    ull r;
    asm("mov.b64 %0, {%1, %1};" : "=l"(r) : "f"(x));
    return r;
}

// ---------------------------------------------------------------------------
// Prologue: transpose codebooks into g_Wt[c][d][k], ||w||^2, zero loss+count.
// ---------------------------------------------------------------------------
__global__ void rvq_prep_kernel(const float* __restrict__ cb) {
    int b = blockIdx.x;              // b = c*1024 + k
    int c = b >> 10, k = b & 1023;
    int t = threadIdx.x;             // t = d
    float v = cb[(size_t)b * DIM + t];
    g_Wt[(size_t)c * DIM * KCB + (size_t)t * KCB + k] = v;
    float s = v * v;
    #pragma unroll
    for (int o = 16; o > 0; o >>= 1) s += __shfl_down_sync(0xffffffffu, s, o);
    __shared__ float red[8];
    if ((t & 31) == 0) red[t >> 5] = s;
    __syncthreads();
    if (t == 0) {
        float n = 0.f;
        #pragma unroll
        for (int w = 0; w < 8; ++w) n += red[w];
        g_wnorm[b] = n;
    }
    if (b == 0 && t < NCB) g_loss[t] = 0.f;
    if (b == 0 && t == NCB) g_count = 0;
}

// ---------------------------------------------------------------------------
// Main fused kernel: 64 rows/CTA resident in SMEM across all 8 codebooks.
// f32x2 SGEMM with 8x8 register tile (128 threads), shuffle argmin,
// fused norms, 2 CTAs/SM. Last CTA writes the final loss.
// ---------------------------------------------------------------------------
__global__ __launch_bounds__(NTHR, 2)
void rvq_main_kernel(const float* __restrict__ z, const float* __restrict__ cb,
                     float* __restrict__ out, int write_extra) {
    extern __shared__ float sm[];
    float* sR  = sm;                       // residual [d][row], stride RST
    float* sW  = sm + OFF_W;               // B tiles, 2 x [TKC][TN]
    float* sRn = sm + OFF_RN;              // row norms [64]
    int*   sBi = (int*)(sm + OFF_BI);      // best idx [64]
    float* sScr= sm + OFF_SCR;             // scratch [128]

    const int tid  = threadIdx.x;
    const int row0 = blockIdx.x * TM;
    const int cg   = tid & 15;             // col group (8 cols), 0..15
    const int rg   = tid >> 4;             // row group (8 rows), 0..7
    // permuted physical 16B-block offsets for this thread's two B blocks
    const int b0 = 2 * cg, b1 = 2 * cg + 1;
    const int pb0 = (b0 ^ ((b0 >> 3) & 1)) * 4;
    const int pb1 = (b1 ^ ((b1 >> 3) & 1)) * 4;

    // Load z tile transposed into SMEM residual (coalesced on d).
    for (int i = tid; i < TM * DIM; i += NTHR) {
        int row = i >> 8, d = i & 255;
        sR[d * RST + row] = z[(size_t)(row0 + row) * DIM + d];
    }
    __syncthreads();

    // Initial per-row ||r||^2 (c = 0 only; later steps get it from the update).
    {
        int q = tid >> 6, row = tid & 63;   // q in {0,1}, 128 dims each
        float s = 0.f;
        #pragma unroll 16
        for (int d = q * 128; d < q * 128 + 128; ++d) {
            float r = sR[d * RST + row];
            s = fmaf(r, r, s);
        }
        sScr[q * 64 + row] = s;
    }
    __syncthreads();
    if (tid < TM)
        sRn[tid] = sScr[tid] + sScr[64 + tid];
    __syncthreads();

    for (int c = 0; c < NCB; ++c) {
        float bv[8]; int bi[8];
        #pragma unroll
        for (int i = 0; i < 8; ++i) { bv[i] = __int_as_float(0x7f800000); bi[i] = 0; }

        // per-row norms for this codebook, hoisted to registers
        float rn[8];
        #pragma unroll
        for (int i = 0; i < 8; ++i) rn[i] = sRn[rg * 8 + i];

        const float* Wc  = g_Wt + (size_t)c * DIM * KCB;
        const float* wnc = g_wnorm + c * KCB;

        for (int nt = 0; nt < NNT; ++nt) {
            const int n0 = nt * TN;

            // prefetch ||w||^2 for this thread's 8 columns (hidden under GEMM)
            float2 wn[4];
            #pragma unroll
            for (int j = 0; j < 4; ++j)
                wn[j] = *(const float2*)(wnc + n0 + cg * 8 + j * 2);

            ull acc[8][4];
            #pragma unroll
            for (int i = 0; i < 8; ++i)
                #pragma unroll
                for (int j = 0; j < 4; ++j) acc[i][j] = 0ull;

            // prefetch chunk 0: TKC x TN floats = 1024 float4, 128 thr x 8
            {
                #pragma unroll
                for (int it = 0; it < 8; ++it) {
                    int idx = tid + it * NTHR;
                    int dd = idx >> 5, j4 = idx & 31;
                    int pj = j4 ^ ((j4 >> 3) & 1);
                    unsigned sa = (unsigned)__cvta_generic_to_shared(sW + dd * TN + pj * 4);
                    const float* gp = Wc + (size_t)dd * KCB + n0 + j4 * 4;
                    asm volatile("cp.async.ca.shared.global [%0], [%1], 16;" :: "r"(sa), "l"(gp));
                }
                asm volatile("cp.async.commit_group;");
            }

            #pragma unroll 1
            for (int dt = 0; dt < NDT; ++dt) {
                if (dt < NDT - 1) {
                    const float* base = Wc + (size_t)(dt + 1) * TKC * KCB;
                    float* dstb = sW + ((dt + 1) & 1) * (TKC * TN);
                    #pragma unroll
                    for (int it = 0; it < 8; ++it) {
                        int idx = tid + it * NTHR;
                        int dd = idx >> 5, j4 = idx & 31;
                        int pj = j4 ^ ((j4 >> 3) & 1);
                        unsigned sa = (unsigned)__cvta_generic_to_shared(dstb + dd * TN + pj * 4);
                        const float* gp = base + (size_t)dd * KCB + n0 + j4 * 4;
                        asm volatile("cp.async.ca.shared.global [%0], [%1], 16;" :: "r"(sa), "l"(gp));
                    }
                    asm volatile("cp.async.commit_group;");
                    asm volatile("cp.async.wait_group 1;");
                } else {
                    asm volatile("cp.async.wait_group 0;");
                }
                __syncthreads();

                const float* As = sR + (dt * TKC) * RST + rg * 8;
                const float* B0 = sW + (dt & 1) * (TKC * TN) + pb0;
                const float* B1 = sW + (dt & 1) * (TKC * TN) + pb1;
                #pragma unroll 4
                for (int dd = 0; dd < TKC; ++dd) {
                    float4 a0 = *(const float4*)(As + dd * RST);
                    float4 a1 = *(const float4*)(As + dd * RST + 4);
                    ulonglong2 bA = *(const ulonglong2*)(B0 + dd * TN);
                    ulonglong2 bB = *(const ulonglong2*)(B1 + dd * TN);
                    float av[8] = {a0.x, a0.y, a0.z, a0.w, a1.x, a1.y, a1.z, a1.w};
                    #pragma unroll
                    for (int i = 0; i < 8; ++i) {
                        ull a2 = dup2(av[i]);
                        acc[i][0] = ffma2(a2, bA.x, acc[i][0]);
                        acc[i][1] = ffma2(a2, bA.y, acc[i][1]);
                        acc[i][2] = ffma2(a2, bB.x, acc[i][2]);
                        acc[i][3] = ffma2(a2, bB.y, acc[i][3]);
                    }
                }
                __syncthreads();
            }

            // epilogue: score = (||r||^2 - 2 s) + ||w||^2, per-row running min
            #pragma unroll
            for (int i = 0; i < 8; ++i) {
                #pragma unroll
                for (int j = 0; j < 4; ++j) {
                    int k0 = n0 + cg * 8 + j * 2;
                    float slo = __uint_as_float((unsigned)(acc[i][j] & 0xffffffffull));
                    float shi = __uint_as_float((unsigned)(acc[i][j] >> 32));
                    float d0 = __fadd_rn(__fadd_rn(rn[i], -2.f * slo), wn[j].x);
                    float d1 = __fadd_rn(__fadd_rn(rn[i], -2.f * shi), wn[j].y);
                    if (d0 < bv[i]) { bv[i] = d0; bi[i] = k0; }
                    if (d1 < bv[i]) { bv[i] = d1; bi[i] = k0 + 1; }
                }
            }
        }

        // ---- shuffle argmin over the 16 cg lanes (a half-warp per rg) ----
        // Packed u64: ordered score bits | idx; min → first-min tie-break.
        #pragma unroll
        for (int i = 0; i < 8; ++i) {
            unsigned m = __float_as_uint(bv[i]);
            m = (m & 0x80000000u) ? ~m : (m | 0x80000000u);
            ull v = ((ull)m << 32) | (unsigned)bi[i];
            #pragma unroll
            for (int off = 1; off < 16; off <<= 1) {
                ull o = __shfl_xor_sync(0xffffffffu, v, off);
                if (o < v) v = o;
            }
            if (cg == 0) {
                int k = (int)(v & 0xffffffffull);
                int row = rg * 8 + i;
                sBi[row] = k;
                if (write_extra)
                    out[Q_ELEMS + (size_t)(row0 + row) * NCB + c] = (float)k;
            }
        }
        __syncthreads();

        // ---- residual update; partial sums double as next step's ||r||^2 ----
        {
            int q = tid >> 6, row = tid & 63;
            int k = sBi[row];
            const float4* wp = (const float4*)(cb + ((size_t)c * KCB + k) * DIM + q * 128);
            float ls = 0.f;
            #pragma unroll
            for (int t4 = 0; t4 < 32; ++t4) {
                float4 w = wp[t4];
                int d = q * 128 + t4 * 4;
                float r0 = sR[(d + 0) * RST + row] - w.x; sR[(d + 0) * RST + row] = r0; ls = fmaf(r0, r0, ls);
                float r1 = sR[(d + 1) * RST + row] - w.y; sR[(d + 1) * RST + row] = r1; ls = fmaf(r1, r1, ls);
                float r2 = sR[(d + 2) * RST + row] - w.z; sR[(d + 2) * RST + row] = r2; ls = fmaf(r2, r2, ls);
                float r3 = sR[(d + 3) * RST + row] - w.w; sR[(d + 3) * RST + row] = r3; ls = fmaf(r3, r3, ls);
            }
            sScr[q * 64 + row] = ls;
        }
        __syncthreads();
        if (tid < TM) {
            float rn2 = sScr[tid] + sScr[64 + tid];
            sRn[tid] = rn2;                // ||r_{c+1}||^2 for next step's scores
            #pragma unroll
            for (int o = 16; o > 0; o >>= 1) rn2 += __shfl_down_sync(0xffffffffu, rn2, o);
            if ((tid & 31) == 0) atomicAdd(&g_loss[c], rn2);
        }
        __syncthreads();
    }

    // ---- quantized = z - residual_final ----
    {
        int q = tid >> 6, row = tid & 63;
        const float* zp = z + (size_t)(row0 + row) * DIM + q * 128;
        float* op = out + (size_t)(row0 + row) * DIM + q * 128;
        #pragma unroll
        for (int t4 = 0; t4 < 32; ++t4) {
            float4 zv = *(const float4*)(zp + t4 * 4);
            int d = q * 128 + t4 * 4;
            float4 r;
            r.x = zv.x - sR[(d + 0) * RST + row];
            r.y = zv.y - sR[(d + 1) * RST + row];
            r.z = zv.z - sR[(d + 2) * RST + row];
            r.w = zv.w - sR[(d + 3) * RST + row];
            *(float4*)(op + t4 * 4) = r;
        }
    }

    // ---- last CTA writes the loss (fin kernel folded in) ----
    if (tid == 0) {
        __threadfence();
        int prev = atomicAdd(&g_count, 1);
        if (prev == (int)gridDim.x - 1) {
            float l = 0.f;
            #pragma unroll
            for (int cc = 0; cc < NCB; ++cc) l += g_loss[cc] * (1.0f / 16777216.0f);
            if (write_extra) out[Q_ELEMS + IDX_ELEMS] = l;
        }
    }
}

extern "C" void kernel_launch(void* const* d_in, const int* in_sizes, int n_in,
                              void* d_out, int out_size) {
    const float* z  = (const float*)d_in[0];
    const float* cb = (const float*)d_in[1];
    if (n_in >= 2 && in_sizes[0] == NCB * KCB * DIM && in_sizes[1] == NROW * DIM) {
        z  = (const float*)d_in[1];
        cb = (const float*)d_in[0];
    }
    float* out = (float*)d_out;
    int write_extra = ((size_t)out_size >= OUT_FULL) ? 1 : 0;

    static const size_t SMEM_BYTES = SMEM_FL * sizeof(float);  // 102,720 B
    cudaFuncSetAttribute(rvq_main_kernel, cudaFuncAttributeMaxDynamicSharedMemorySize,
                         (int)SMEM_BYTES);

    rvq_prep_kernel<<<NCB * KCB, 256>>>(cb);
    rvq_main_kernel<<<NROW / TM, NTHR, SMEM_BYTES>>>(z, cb, out, write_extra);
}

// round 9
// speedup vs baseline: 1.2775x; 1.0013x over previous
#include <cuda_runtime.h>
#include <cstdint>

// Residual VQ fused kernel for B200 (sm_100a).
// z [65536, 256] f32, codebooks [8, 1024, 256] f32.
// Output: concat(quantized [65536*256], indices [65536*8] as f32, loss [1]).

#define NCB   8
#define KCB   1024
#define DIM   256
#define NROW  65536
#define TM    64       // rows per CTA
#define TN    128      // codewords per n-tile
#define TKC   32       // reduction chunk
#define NTHR  128
#define RST   68       // residual smem row stride (floats), 68*4 % 16 == 0
#define NDT   (DIM / TKC)   // 8
#define NNT   (KCB / TN)    // 8

#define Q_ELEMS   ((size_t)NROW * DIM)            // 16777216
#define IDX_ELEMS ((size_t)NROW * NCB)            // 524288
#define OUT_FULL  (Q_ELEMS + IDX_ELEMS + 1)       // 17301505

// SMEM float offsets
#define OFF_W    17408                      // sR = [256][68] = 17408 floats
#define OFF_RN   (OFF_W + 2 * TKC * TN)     // sW double buffer = 8192 fl
#define OFF_BI   (OFF_RN + 64)
#define OFF_SCR  (OFF_BI + 64)
#define SMEM_FL  (OFF_SCR + 128 + 16)       // = 25680 floats = 102,720 B

typedef unsigned long long ull;

__device__ float g_Wt[(size_t)NCB * DIM * KCB];   // codebooks transposed: [c][d][k]
__device__ float g_wnorm[NCB * KCB];              // ||w||^2 per codeword
__device__ float g_loss[NCB];                     // per-step sum of residual^2
__device__ int   g_count;                         // CTA completion counter

__device__ __forceinline__ ull ffma2(ull a, ull b, ull c) {
    ull d;
    asm("fma.rn.f32x2 %0, %1, %2, %3;" : "=l"(d) : "l"(a), "l"(b), "l"(c));
    return d;
}
__device__ __forceinline__ ull dup2(float x) {
    ull r;
    asm("mov.b64 %0, {%1, %1};" : "=l"(r) : "f"(x));
    return r;
}

// ---------------------------------------------------------------------------
// Prologue: transpose codebooks into g_Wt[c][d][k], ||w||^2, zero loss+count.
// ---------------------------------------------------------------------------
__global__ void rvq_prep_kernel(const float* __restrict__ cb) {
    int b = blockIdx.x;              // b = c*1024 + k
    int c = b >> 10, k = b & 1023;
    int t = threadIdx.x;             // t = d
    float v = cb[(size_t)b * DIM + t];
    g_Wt[(size_t)c * DIM * KCB + (size_t)t * KCB + k] = v;
    float s = v * v;
    #pragma unroll
    for (int o = 16; o > 0; o >>= 1) s += __shfl_down_sync(0xffffffffu, s, o);
    __shared__ float red[8];
    if ((t & 31) == 0) red[t >> 5] = s;
    __syncthreads();
    if (t == 0) {
        float n = 0.f;
        #pragma unroll
        for (int w = 0; w < 8; ++w) n += red[w];
        g_wnorm[b] = n;
    }
    if (b == 0 && t < NCB) g_loss[t] = 0.f;
    if (b == 0 && t == NCB) g_count = 0;
}

// ---------------------------------------------------------------------------
// Main fused kernel: 64 rows/CTA resident in SMEM across all 8 codebooks.
// f32x2 SGEMM with 8x8 register tile (128 threads), shuffle argmin,
// fused norms, 2 CTAs/SM. Last CTA writes the final loss.
// ---------------------------------------------------------------------------
__global__ __launch_bounds__(NTHR, 2)
void rvq_main_kernel(const float* __restrict__ z, const float* __restrict__ cb,
                     float* __restrict__ out, int write_extra) {
    extern __shared__ float sm[];
    float* sR  = sm;                       // residual [d][row], stride RST
    float* sW  = sm + OFF_W;               // B tiles, 2 x [TKC][TN]
    float* sRn = sm + OFF_RN;              // row norms [64]
    int*   sBi = (int*)(sm + OFF_BI);      // best idx [64]
    float* sScr= sm + OFF_SCR;             // scratch [128]

    const int tid  = threadIdx.x;
    const int row0 = blockIdx.x * TM;
    const int cg   = tid & 15;             // col group (8 cols), 0..15
    const int rg   = tid >> 4;             // row group (8 rows), 0..7
    // permuted physical 16B-block offsets for this thread's two B blocks
    const int b0 = 2 * cg, b1 = 2 * cg + 1;
    const int pb0 = (b0 ^ ((b0 >> 3) & 1)) * 4;
    const int pb1 = (b1 ^ ((b1 >> 3) & 1)) * 4;

    // Load z tile transposed into SMEM residual (coalesced on d).
    for (int i = tid; i < TM * DIM; i += NTHR) {
        int row = i >> 8, d = i & 255;
        sR[d * RST + row] = z[(size_t)(row0 + row) * DIM + d];
    }
    __syncthreads();

    // Initial per-row ||r||^2 (c = 0 only; later steps get it from the update).
    {
        int q = tid >> 6, row = tid & 63;   // q in {0,1}, 128 dims each
        float s = 0.f;
        #pragma unroll 16
        for (int d = q * 128; d < q * 128 + 128; ++d) {
            float r = sR[d * RST + row];
            s = fmaf(r, r, s);
        }
        sScr[q * 64 + row] = s;
    }
    __syncthreads();
    if (tid < TM)
        sRn[tid] = sScr[tid] + sScr[64 + tid];
    __syncthreads();

    for (int c = 0; c < NCB; ++c) {
        float bv[8]; int bi[8];
        #pragma unroll
        for (int i = 0; i < 8; ++i) { bv[i] = __int_as_float(0x7f800000); bi[i] = 0; }

        // per-row norms for this codebook, hoisted to registers
        float rn[8];
        #pragma unroll
        for (int i = 0; i < 8; ++i) rn[i] = sRn[rg * 8 + i];

        const float* Wc  = g_Wt + (size_t)c * DIM * KCB;
        const float* wnc = g_wnorm + c * KCB;

        for (int nt = 0; nt < NNT; ++nt) {
            const int n0 = nt * TN;

            // prefetch ||w||^2 for this thread's 8 columns (hidden under GEMM)
            float2 wn[4];
            #pragma unroll
            for (int j = 0; j < 4; ++j)
                wn[j] = *(const float2*)(wnc + n0 + cg * 8 + j * 2);

            ull acc[8][4];
            #pragma unroll
            for (int i = 0; i < 8; ++i)
                #pragma unroll
                for (int j = 0; j < 4; ++j) acc[i][j] = 0ull;

            // prefetch chunk 0: TKC x TN floats = 1024 float4, 128 thr x 8
            {
                #pragma unroll
                for (int it = 0; it < 8; ++it) {
                    int idx = tid + it * NTHR;
                    int dd = idx >> 5, j4 = idx & 31;
                    int pj = j4 ^ ((j4 >> 3) & 1);
                    unsigned sa = (unsigned)__cvta_generic_to_shared(sW + dd * TN + pj * 4);
                    const float* gp = Wc + (size_t)dd * KCB + n0 + j4 * 4;
                    asm volatile("cp.async.ca.shared.global [%0], [%1], 16;" :: "r"(sa), "l"(gp));
                }
                asm volatile("cp.async.commit_group;");
            }

            #pragma unroll 1
            for (int dt = 0; dt < NDT; ++dt) {
                if (dt < NDT - 1) {
                    const float* base = Wc + (size_t)(dt + 1) * TKC * KCB;
                    float* dstb = sW + ((dt + 1) & 1) * (TKC * TN);
                    #pragma unroll
                    for (int it = 0; it < 8; ++it) {
                        int idx = tid + it * NTHR;
                        int dd = idx >> 5, j4 = idx & 31;
                        int pj = j4 ^ ((j4 >> 3) & 1);
                        unsigned sa = (unsigned)__cvta_generic_to_shared(dstb + dd * TN + pj * 4);
                        const float* gp = base + (size_t)dd * KCB + n0 + j4 * 4;
                        asm volatile("cp.async.ca.shared.global [%0], [%1], 16;" :: "r"(sa), "l"(gp));
                    }
                    asm volatile("cp.async.commit_group;");
                    asm volatile("cp.async.wait_group 1;");
                } else {
                    asm volatile("cp.async.wait_group 0;");
                }
                __syncthreads();

                const float* As = sR + (dt * TKC) * RST + rg * 8;
                const float* B0 = sW + (dt & 1) * (TKC * TN) + pb0;
                const float* B1 = sW + (dt & 1) * (TKC * TN) + pb1;
                #pragma unroll 4
                for (int dd = 0; dd < TKC; ++dd) {
                    float4 a0 = *(const float4*)(As + dd * RST);
                    float4 a1 = *(const float4*)(As + dd * RST + 4);
                    ulonglong2 bA = *(const ulonglong2*)(B0 + dd * TN);
                    ulonglong2 bB = *(const ulonglong2*)(B1 + dd * TN);
                    float av[8] = {a0.x, a0.y, a0.z, a0.w, a1.x, a1.y, a1.z, a1.w};
                    #pragma unroll
                    for (int i = 0; i < 8; ++i) {
                        ull a2 = dup2(av[i]);
                        acc[i][0] = ffma2(a2, bA.x, acc[i][0]);
                        acc[i][1] = ffma2(a2, bA.y, acc[i][1]);
                        acc[i][2] = ffma2(a2, bB.x, acc[i][2]);
                        acc[i][3] = ffma2(a2, bB.y, acc[i][3]);
                    }
                }
                __syncthreads();
            }

            // epilogue: score = (||r||^2 - 2 s) + ||w||^2, per-row running min
            #pragma unroll
            for (int i = 0; i < 8; ++i) {
                #pragma unroll
                for (int j = 0; j < 4; ++j) {
                    int k0 = n0 + cg * 8 + j * 2;
                    float slo = __uint_as_float((unsigned)(acc[i][j] & 0xffffffffull));
                    float shi = __uint_as_float((unsigned)(acc[i][j] >> 32));
                    float d0 = __fadd_rn(__fadd_rn(rn[i], -2.f * slo), wn[j].x);
                    float d1 = __fadd_rn(__fadd_rn(rn[i], -2.f * shi), wn[j].y);
                    if (d0 < bv[i]) { bv[i] = d0; bi[i] = k0; }
                    if (d1 < bv[i]) { bv[i] = d1; bi[i] = k0 + 1; }
                }
            }
        }

        // ---- shuffle argmin over the 16 cg lanes (a half-warp per rg) ----
        // Packed u64: ordered score bits | idx; min → first-min tie-break.
        #pragma unroll
        for (int i = 0; i < 8; ++i) {
            unsigned m = __float_as_uint(bv[i]);
            m = (m & 0x80000000u) ? ~m : (m | 0x80000000u);
            ull v = ((ull)m << 32) | (unsigned)bi[i];
            #pragma unroll
            for (int off = 1; off < 16; off <<= 1) {
                ull o = __shfl_xor_sync(0xffffffffu, v, off);
                if (o < v) v = o;
            }
            if (cg == 0) {
                int k = (int)(v & 0xffffffffull);
                int row = rg * 8 + i;
                sBi[row] = k;
                if (write_extra)
                    out[Q_ELEMS + (size_t)(row0 + row) * NCB + c] = (float)k;
            }
        }
        __syncthreads();

        // ---- residual update; partial sums double as next step's ||r||^2 ----
        {
            int q = tid >> 6, row = tid & 63;
            int k = sBi[row];
            const float4* wp = (const float4*)(cb + ((size_t)c * KCB + k) * DIM + q * 128);
            float ls = 0.f;
            #pragma unroll
            for (int t4 = 0; t4 < 32; ++t4) {
                float4 w = wp[t4];
                int d = q * 128 + t4 * 4;
                float r0 = sR[(d + 0) * RST + row] - w.x; sR[(d + 0) * RST + row] = r0; ls = fmaf(r0, r0, ls);
                float r1 = sR[(d + 1) * RST + row] - w.y; sR[(d + 1) * RST + row] = r1; ls = fmaf(r1, r1, ls);
                float r2 = sR[(d + 2) * RST + row] - w.z; sR[(d + 2) * RST + row] = r2; ls = fmaf(r2, r2, ls);
                float r3 = sR[(d + 3) * RST + row] - w.w; sR[(d + 3) * RST + row] = r3; ls = fmaf(r3, r3, ls);
            }
            sScr[q * 64 + row] = ls;
        }
        __syncthreads();
        if (tid < TM) {
            float rn2 = sScr[tid] + sScr[64 + tid];
            sRn[tid] = rn2;                // ||r_{c+1}||^2 for next step's scores
            #pragma unroll
            for (int o = 16; o > 0; o >>= 1) rn2 += __shfl_down_sync(0xffffffffu, rn2, o);
            if ((tid & 31) == 0) atomicAdd(&g_loss[c], rn2);
        }
        __syncthreads();
    }

    // ---- quantized = z - residual_final ----
    {
        int q = tid >> 6, row = tid & 63;
        const float* zp = z + (size_t)(row0 + row) * DIM + q * 128;
        float* op = out + (size_t)(row0 + row) * DIM + q * 128;
        #pragma unroll
        for (int t4 = 0; t4 < 32; ++t4) {
            float4 zv = *(const float4*)(zp + t4 * 4);
            int d = q * 128 + t4 * 4;
            float4 r;
            r.x = zv.x - sR[(d + 0) * RST + row];
            r.y = zv.y - sR[(d + 1) * RST + row];
            r.z = zv.z - sR[(d + 2) * RST + row];
            r.w = zv.w - sR[(d + 3) * RST + row];
            *(float4*)(op + t4 * 4) = r;
        }
    }

    // ---- last CTA writes the loss (fin kernel folded in) ----
    if (tid == 0) {
        __threadfence();
        int prev = atomicAdd(&g_count, 1);
        if (prev == (int)gridDim.x - 1) {
            float l = 0.f;
            #pragma unroll
            for (int cc = 0; cc < NCB; ++cc) l += g_loss[cc] * (1.0f / 16777216.0f);
            if (write_extra) out[Q_ELEMS + IDX_ELEMS] = l;
        }
    }
}

extern "C" void kernel_launch(void* const* d_in, const int* in_sizes, int n_in,
                              void* d_out, int out_size) {
    const float* z  = (const float*)d_in[0];
    const float* cb = (const float*)d_in[1];
    if (n_in >= 2 && in_sizes[0] == NCB * KCB * DIM && in_sizes[1] == NROW * DIM) {
        z  = (const float*)d_in[1];
        cb = (const float*)d_in[0];
    }
    float* out = (float*)d_out;
    int write_extra = ((size_t)out_size >= OUT_FULL) ? 1 : 0;

    static const size_t SMEM_BYTES = SMEM_FL * sizeof(float);  // 102,720 B

    // One-time function attributes. The carveout is the critical one: without
    // it the driver picks a 132KB L1/shared split (just enough for ONE block)
    // and occupancy silently drops to 1 CTA/SM. 100 => max-shared (228KB
    // config) so two 102.7KB CTAs co-reside.
    static bool configured = false;
    if (!configured) {
        cudaFuncSetAttribute(rvq_main_kernel,
                             cudaFuncAttributeMaxDynamicSharedMemorySize,
                             (int)SMEM_BYTES);
        cudaFuncSetAttribute(rvq_main_kernel,
                             cudaFuncAttributePreferredSharedMemoryCarveout,
                             100);
        configured = true;
    }

    rvq_prep_kernel<<<NCB * KCB, 256>>>(cb);
    rvq_main_kernel<<<NROW / TM, NTHR, SMEM_BYTES>>>(z, cb, out, write_extra);
}